// round 14
// baseline (speedup 1.0000x reference)
#include <cuda_runtime.h>
#include <cuda_bf16.h>
#include <math.h>
#include <float.h>

#define NB 16
#define NT 128
#define NK 1024
#define ND 768
#define NKP 102
#define NBT (NB*NT)
#define INV_SQRT_D 0.03608439182435161f
#define NEG_INF (-3.402823466e38f)

// ---------------- device scratch (no allocations allowed) ----------------
__device__ __align__(16) static float g_emission[NBT * NK];     // 8 MB
__device__ __align__(16) static float g_transition[NK * NK];    // 4 MB (symmetric)
__device__ __align__(16) static float g_alpha_sum[2][NB * NK];
__device__ __align__(16) static float g_alpha_vit[2][NB * NK];
__device__ static unsigned short g_bp[(NT - 1) * NB * NK];      // backpointers
__device__ __align__(16) static float g_emtop[NBT * NKP];
__device__ __align__(16) static int   g_topidx[NBT * NKP];
__device__ __align__(16) static float g_appx[2][NB * NKP];
__device__ static float g_rowlse[NBT];
__device__ static float g_maxprob[NBT];
__device__ static float g_emy[NBT];
__device__ static int   g_smpred[NBT];
__device__ static float g_logZ[NB];
__device__ static float g_logZa[NB];
__device__ static int   g_crf[NBT];

// grid barrier state (returns to {cnt=0} after each full barrier; epoch monotonic)
__device__ unsigned g_barcnt = 0;
__device__ unsigned g_barep  = 0;

// ---------------- GEMM: C[M,N] = scale * A[.,768] * B[.,768]^T ----------------
__device__ __forceinline__ void gemm_body(const float* __restrict__ A,
                                          const float* __restrict__ B,
                                          float* __restrict__ C,
                                          int N, float scale)
{
    __shared__ __align__(16) float As[16][64];
    __shared__ __align__(16) float Bs[16][64];
    int tid = threadIdx.x;
    int tx = tid & 15, ty = tid >> 4;
    int m0 = blockIdx.y * 64, n0 = blockIdx.x * 64;
    int lr = tid >> 2;            // 0..63
    int lc = (tid & 3) << 2;      // 0,4,8,12
    float acc[4][4];
#pragma unroll
    for (int i = 0; i < 4; i++)
#pragma unroll
        for (int j = 0; j < 4; j++) acc[i][j] = 0.f;

    for (int d0 = 0; d0 < ND; d0 += 16) {
        float4 a4 = *(const float4*)(A + (size_t)(m0 + lr) * ND + d0 + lc);
        float4 b4 = *(const float4*)(B + (size_t)(n0 + lr) * ND + d0 + lc);
        As[lc + 0][lr] = a4.x; As[lc + 1][lr] = a4.y; As[lc + 2][lr] = a4.z; As[lc + 3][lr] = a4.w;
        Bs[lc + 0][lr] = b4.x; Bs[lc + 1][lr] = b4.y; Bs[lc + 2][lr] = b4.z; Bs[lc + 3][lr] = b4.w;
        __syncthreads();
#pragma unroll
        for (int kk = 0; kk < 16; kk++) {
            float4 av = *(const float4*)(&As[kk][ty * 4]);
            float4 bv = *(const float4*)(&Bs[kk][tx * 4]);
            acc[0][0] += av.x * bv.x; acc[0][1] += av.x * bv.y; acc[0][2] += av.x * bv.z; acc[0][3] += av.x * bv.w;
            acc[1][0] += av.y * bv.x; acc[1][1] += av.y * bv.y; acc[1][2] += av.y * bv.z; acc[1][3] += av.y * bv.w;
            acc[2][0] += av.z * bv.x; acc[2][1] += av.z * bv.y; acc[2][2] += av.z * bv.z; acc[2][3] += av.z * bv.w;
            acc[3][0] += av.w * bv.x; acc[3][1] += av.w * bv.y; acc[3][2] += av.w * bv.z; acc[3][3] += av.w * bv.w;
        }
        __syncthreads();
    }
#pragma unroll
    for (int i = 0; i < 4; i++) {
        float4 o;
        o.x = acc[i][0] * scale; o.y = acc[i][1] * scale;
        o.z = acc[i][2] * scale; o.w = acc[i][3] * scale;
        *(float4*)(C + (size_t)(m0 + ty * 4 + i) * N + n0 + tx * 4) = o;
    }
}

__global__ __launch_bounds__(256) void k_gemm_em(const float* __restrict__ x,
                                                 const float* __restrict__ S)
{ gemm_body(x, S, g_emission, NK, INV_SQRT_D); }

__global__ __launch_bounds__(256) void k_gemm_tr(const float* __restrict__ S)
{ gemm_body(S, S, g_transition, NK, INV_SQRT_D); }

// ---------------- top-k (bitonic sort; slot order is irrelevant downstream) ----------------
__global__ __launch_bounds__(512) void topk_kernel(const int* __restrict__ y_lens)
{
    int row = blockIdx.x;
    int b = row >> 7, t = row & 127;
    if (t >= y_lens[b]) return;
    __shared__ float sv[NK];
    __shared__ int   si[NK];
    int tid = threadIdx.x;
    const float* em = g_emission + (size_t)row * NK;
    sv[tid] = em[tid];             si[tid] = tid;
    sv[tid + 512] = em[tid + 512]; si[tid + 512] = tid + 512;
    __syncthreads();
    for (int k = 2; k <= NK; k <<= 1) {
        for (int j = k >> 1; j > 0; j >>= 1) {
#pragma unroll 1
            for (int base = 0; base < NK; base += 512) {
                int i = base + tid;
                int ixj = i ^ j;
                if (ixj > i) {
                    bool up = ((i & k) == 0);
                    float a = sv[i], c = sv[ixj];
                    if ((a > c) == up) {
                        sv[i] = c; sv[ixj] = a;
                        int tmp = si[i]; si[i] = si[ixj]; si[ixj] = tmp;
                    }
                }
            }
            __syncthreads();
        }
    }
    if (tid < NKP) {
        g_emtop[(size_t)row * NKP + tid]  = sv[NK - NKP + tid];
        g_topidx[(size_t)row * NKP + tid] = si[NK - NKP + tid];
    }
}

// ---------------- per-row: lse, argmax(first-idx), max softmax prob, em_y ----------------
__global__ __launch_bounds__(256) void rowstats_kernel(const int* __restrict__ y)
{
    int row = blockIdx.x * 8 + (threadIdx.x >> 5);
    int lane = threadIdx.x & 31;
    const float* em = g_emission + (size_t)row * NK;
    float m = NEG_INF; int mi = 0;
    for (int i = lane; i < NK; i += 32) {
        float v = em[i];
        if (v > m) { m = v; mi = i; }
    }
#pragma unroll
    for (int off = 16; off; off >>= 1) {
        float om = __shfl_xor_sync(0xffffffffu, m, off);
        int   oi = __shfl_xor_sync(0xffffffffu, mi, off);
        if (om > m || (om == m && oi < mi)) { m = om; mi = oi; }
    }
    float s = 0.f;
    for (int i = lane; i < NK; i += 32) s += expf(em[i] - m);
#pragma unroll
    for (int off = 16; off; off >>= 1) s += __shfl_xor_sync(0xffffffffu, s, off);
    if (lane == 0) {
        float lse = m + logf(s);
        g_rowlse[row]  = lse;
        g_smpred[row]  = mi;
        g_maxprob[row] = expf(m - lse);
        g_emy[row]     = em[y[row]];
    }
}

// ---------------- grid barrier among the 128 main CTAs ----------------
// No CCTL/L1-flush: gpu-scope release atomic + acquire-load spin; data
// exchanged via __ldcv (L1-bypass) so only L2 visibility is needed.
__device__ __forceinline__ void grid_bar()
{
    __syncthreads();
    if (threadIdx.x == 0) {
        unsigned e0, e, p;
        asm volatile("ld.acquire.gpu.b32 %0, [%1];" : "=r"(e0) : "l"(&g_barep) : "memory");
        asm volatile("atom.add.release.gpu.u32 %0, [%1], %2;"
                     : "=r"(p) : "l"(&g_barcnt), "r"(1u) : "memory");
        if (p == 127u) {
            asm volatile("st.relaxed.gpu.b32 [%0], %1;" :: "l"(&g_barcnt), "r"(0u) : "memory");
            asm volatile("red.add.release.gpu.u32 [%0], %1;" :: "l"(&g_barep), "r"(1u) : "memory");
        } else {
            do {
                asm volatile("ld.acquire.gpu.b32 %0, [%1];" : "=r"(e) : "l"(&g_barep) : "memory");
            } while (e == e0);
        }
    }
    __syncthreads();
}

// ---------------- persistent recursion kernel ----------------
// CTAs 0..127: each owns 8 j-columns for ALL batches; T rows live in registers
// for the whole run (zero per-step T traffic). Per step: stage prev alphas of
// active batches into SMEM (ldcv), compute sum-forward (linearized exp) +
// Viterbi. CTAs 128..143: approx forward, one per batch (no barrier).
__global__ __launch_bounds__(128, 1)
void persist2(const int* __restrict__ y_lens)
{
    extern __shared__ float dynsmem[];
    float* shW = dynsmem;            // [16][1024] exp'ed weights
    float* shV = dynsmem + 16384;    // [16][1024] viterbi alphas
    __shared__ float shSh[NB];
    __shared__ float shEp[NB][4];
    __shared__ int   shLen[NB];

    int cta = blockIdx.x;
    int tid = threadIdx.x;

    if (cta < 128) {
        int wid = tid >> 5, lane = tid & 31;
        int j0 = cta * 8 + wid * 2, j1 = j0 + 1;

        if (tid < NB) shLen[tid] = y_lens[tid];
        __syncthreads();
        int maxlen = 1;
#pragma unroll
        for (int b = 0; b < NB; b++) maxlen = max(maxlen, shLen[b]);

        // T rows (symmetric: T[i][j]==T[j][i]) register-resident for all steps.
        float tA[32], tB[32];
#pragma unroll
        for (int n = 0; n < 8; n++) {
            float4 q = __ldg((const float4*)(g_transition + (size_t)j0 * NK + n * 128 + (lane << 2)));
            tA[n*4+0]=q.x; tA[n*4+1]=q.y; tA[n*4+2]=q.z; tA[n*4+3]=q.w;
            float4 r = __ldg((const float4*)(g_transition + (size_t)j1 * NK + n * 128 + (lane << 2)));
            tB[n*4+0]=r.x; tB[n*4+1]=r.y; tB[n*4+2]=r.z; tB[n*4+3]=r.w;
        }

        // t = 0 init: my 8 j for all 16 batches (128 values, one per thread)
        {
            int b = tid >> 3, jj = tid & 7;
            int j = cta * 8 + jj;
            float e = g_emission[(size_t)(b << 7) * NK + j];
            g_alpha_sum[0][(b << 10) + j] = e;
            g_alpha_vit[0][(b << 10) + j] = e;
        }

        for (int t = 1; t < maxlen; t++) {
            grid_bar();   // prev-step alpha writes of ALL CTAs now visible (L2)

            const float* prevS = g_alpha_sum[(t - 1) & 1];
            const float* prevV = g_alpha_vit[(t - 1) & 1];
            float* curS = g_alpha_sum[t & 1];
            float* curV = g_alpha_vit[t & 1];

            if (tid < NB)
                shSh[tid] = (t < shLen[tid]) ? __ldcv(prevS + (tid << 10)) : 0.f;
            __syncthreads();

            // ---- stage active batches: w = exp(prevS - shift), V raw ----
#pragma unroll 1
            for (int b = 0; b < NB; b++) {
                if (t >= shLen[b]) continue;
                const float4* pS = (const float4*)(prevS + (b << 10));
                const float4* pV = (const float4*)(prevV + (b << 10));
                float shift = shSh[b];
                float4 s0 = __ldcv(pS + tid);
                float4 s1 = __ldcv(pS + 128 + tid);
                float4 v0 = __ldcv(pV + tid);
                float4 v1 = __ldcv(pV + 128 + tid);
                float4 w0, w1;
                w0.x = __expf(s0.x - shift); w0.y = __expf(s0.y - shift);
                w0.z = __expf(s0.z - shift); w0.w = __expf(s0.w - shift);
                w1.x = __expf(s1.x - shift); w1.y = __expf(s1.y - shift);
                w1.z = __expf(s1.z - shift); w1.w = __expf(s1.w - shift);
                ((float4*)(shW + (b << 10)))[tid]       = w0;
                ((float4*)(shW + (b << 10)))[128 + tid] = w1;
                ((float4*)(shV + (b << 10)))[tid]       = v0;
                ((float4*)(shV + (b << 10)))[128 + tid] = v1;
                float ps = ((w0.x + w0.y) + (w0.z + w0.w))
                         + ((w1.x + w1.y) + (w1.z + w1.w));
#pragma unroll
                for (int off = 16; off; off >>= 1)
                    ps += __shfl_xor_sync(0xffffffffu, ps, off);
                if (lane == 0) shEp[b][wid] = ps;
            }
            __syncthreads();

            // ---- compute: per warp, 2 j-columns over all active batches ----
#pragma unroll 1
            for (int b = 0; b < NB; b++) {
                if (t >= shLen[b]) continue;
                float E = (shEp[b][0] + shEp[b][1]) + (shEp[b][2] + shEp[b][3]);
                float shift = shSh[b];
                float em0 = __ldg(g_emission + (size_t)((b << 7) + t) * NK + j0);
                float em1 = __ldg(g_emission + (size_t)((b << 7) + t) * NK + j1);
                const float* wb = shW + (b << 10);
                const float* vb = shV + (b << 10);
                float acc0 = 0.f, acc1 = 0.f, m0 = NEG_INF, m1 = NEG_INF;
                int id0 = 0, id1 = 0;
#pragma unroll
                for (int n = 0; n < 8; n++) {
                    int ib = n * 128 + (lane << 2);
                    float4 w4 = *(const float4*)(wb + ib);
                    float4 v4 = *(const float4*)(vb + ib);
                    float u;
                    acc0 = fmaf(w4.x, tA[n*4+0], acc0);
                    u = v4.x + tA[n*4+0]; if (u > m0) { m0 = u; id0 = ib; }
                    acc0 = fmaf(w4.y, tA[n*4+1], acc0);
                    u = v4.y + tA[n*4+1]; if (u > m0) { m0 = u; id0 = ib + 1; }
                    acc0 = fmaf(w4.z, tA[n*4+2], acc0);
                    u = v4.z + tA[n*4+2]; if (u > m0) { m0 = u; id0 = ib + 2; }
                    acc0 = fmaf(w4.w, tA[n*4+3], acc0);
                    u = v4.w + tA[n*4+3]; if (u > m0) { m0 = u; id0 = ib + 3; }

                    acc1 = fmaf(w4.x, tB[n*4+0], acc1);
                    u = v4.x + tB[n*4+0]; if (u > m1) { m1 = u; id1 = ib; }
                    acc1 = fmaf(w4.y, tB[n*4+1], acc1);
                    u = v4.y + tB[n*4+1]; if (u > m1) { m1 = u; id1 = ib + 1; }
                    acc1 = fmaf(w4.z, tB[n*4+2], acc1);
                    u = v4.z + tB[n*4+2]; if (u > m1) { m1 = u; id1 = ib + 2; }
                    acc1 = fmaf(w4.w, tB[n*4+3], acc1);
                    u = v4.w + tB[n*4+3]; if (u > m1) { m1 = u; id1 = ib + 3; }
                }
#pragma unroll
                for (int off = 16; off; off >>= 1) {
                    acc0 += __shfl_xor_sync(0xffffffffu, acc0, off);
                    acc1 += __shfl_xor_sync(0xffffffffu, acc1, off);
                    float o0 = __shfl_xor_sync(0xffffffffu, m0, off);
                    int   q0 = __shfl_xor_sync(0xffffffffu, id0, off);
                    if (o0 > m0 || (o0 == m0 && q0 < id0)) { m0 = o0; id0 = q0; }
                    float o1 = __shfl_xor_sync(0xffffffffu, m1, off);
                    int   q1 = __shfl_xor_sync(0xffffffffu, id1, off);
                    if (o1 > m1 || (o1 == m1 && q1 < id1)) { m1 = o1; id1 = q1; }
                }
                if (lane == 0) {
                    // sum_i exp(aS_i + T_ij) = E + sum_i w_i T_ij  (exp(T)=1+T exact to <ulp)
                    curS[(b << 10) + j0] = shift + __logf(E + acc0) + em0;
                    curV[(b << 10) + j0] = m0 + em0;
                    g_bp[(size_t)(t - 1) * (NB * NK) + (b << 10) + j0] = (unsigned short)id0;
                    curS[(b << 10) + j1] = shift + __logf(E + acc1) + em1;
                    curV[(b << 10) + j1] = m1 + em1;
                    g_bp[(size_t)(t - 1) * (NB * NK) + (b << 10) + j1] = (unsigned short)id1;
                }
            }
        }
    } else {
        // -------- approx forward, one CTA per batch (independent chain) --------
        int ba = cta - 128;
        int len = y_lens[ba];
        __shared__ float pA[NKP];
        __shared__ int   pI[NKP];
        __shared__ float pW[NKP];
        __shared__ float sEa;

        if (tid < NKP)
            g_appx[0][ba * NKP + tid] = g_emtop[(size_t)(ba << 7) * NKP + tid];
        __syncthreads();

        for (int t = 1; t < len; t++) {
            int row = (ba << 7) + t, prow = row - 1;
            if (tid < NKP) {
                pA[tid] = g_appx[(t - 1) & 1][ba * NKP + tid];
                pI[tid] = g_topidx[(size_t)prow * NKP + tid];
            }
            __syncthreads();
            float shift = pA[0];
            if (tid < NKP) pW[tid] = __expf(pA[tid] - shift);
            __syncthreads();
            if (tid == 0) {
                float e = 0.f;
                for (int i = 0; i < NKP; i++) e += pW[i];
                sEa = e;
            }
            __syncthreads();
            if (tid < NKP) {
                int jc = g_topidx[(size_t)row * NKP + tid];
                const float* Tc = g_transition + jc;
                float s0 = 0.f, s1 = 0.f, s2 = 0.f, s3 = 0.f;
#pragma unroll 2
                for (int i = 0; i + 4 <= NKP; i += 4) {
                    float t0 = __ldg(Tc + (size_t)pI[i + 0] * NK);
                    float t1 = __ldg(Tc + (size_t)pI[i + 1] * NK);
                    float t2 = __ldg(Tc + (size_t)pI[i + 2] * NK);
                    float t3 = __ldg(Tc + (size_t)pI[i + 3] * NK);
                    s0 = fmaf(pW[i + 0], t0, s0);
                    s1 = fmaf(pW[i + 1], t1, s1);
                    s2 = fmaf(pW[i + 2], t2, s2);
                    s3 = fmaf(pW[i + 3], t3, s3);
                }
                s0 = fmaf(pW[100], __ldg(Tc + (size_t)pI[100] * NK), s0);
                s1 = fmaf(pW[101], __ldg(Tc + (size_t)pI[101] * NK), s1);
                float s = ((s0 + s1) + (s2 + s3)) + sEa;
                g_appx[t & 1][ba * NKP + tid] =
                    shift + __logf(s) + g_emtop[(size_t)row * NKP + tid];
            }
            __syncthreads();
        }
    }
}

// ---------------- last-state / log_Z / backtrace ----------------
__global__ __launch_bounds__(512) void trace_kernel(const int* __restrict__ y_lens,
                                                    float* __restrict__ out)
{
    __shared__ int sh_last[NB];
    int tid = threadIdx.x;
    int b = tid >> 5, lane = tid & 31;
    int len = y_lens[b];
    int par = (len - 1) & 1;
    {   // argmax of viterbi a_last (first index on ties)
        const float* av = g_alpha_vit[par] + (b << 10);
        float m = NEG_INF; int mi = 0;
        for (int j = lane; j < NK; j += 32) {
            float v = av[j];
            if (v > m) { m = v; mi = j; }
        }
#pragma unroll
        for (int off = 16; off; off >>= 1) {
            float om = __shfl_xor_sync(0xffffffffu, m, off);
            int   oi = __shfl_xor_sync(0xffffffffu, mi, off);
            if (om > m || (om == m && oi < mi)) { m = om; mi = oi; }
        }
        if (lane == 0) sh_last[b] = mi;
    }
    {   // log_Z (exact)
        const float* as = g_alpha_sum[par] + (b << 10);
        float m = NEG_INF;
        for (int j = lane; j < NK; j += 32) m = fmaxf(m, as[j]);
#pragma unroll
        for (int off = 16; off; off >>= 1) m = fmaxf(m, __shfl_xor_sync(0xffffffffu, m, off));
        float s = 0.f;
        for (int j = lane; j < NK; j += 32) s += expf(as[j] - m);
#pragma unroll
        for (int off = 16; off; off >>= 1) s += __shfl_xor_sync(0xffffffffu, s, off);
        if (lane == 0) g_logZ[b] = m + logf(s);
    }
    {   // log_Z approx
        const float* aa = g_appx[par] + b * NKP;
        float m = NEG_INF;
        for (int j = lane; j < NKP; j += 32) m = fmaxf(m, aa[j]);
#pragma unroll
        for (int off = 16; off; off >>= 1) m = fmaxf(m, __shfl_xor_sync(0xffffffffu, m, off));
        float s = 0.f;
        for (int j = lane; j < NKP; j += 32) s += expf(aa[j] - m);
#pragma unroll
        for (int off = 16; off; off >>= 1) s += __shfl_xor_sync(0xffffffffu, s, off);
        if (lane == 0) g_logZa[b] = m + logf(s);
    }
    __syncthreads();
    if (tid < NB) {
        int bb = tid;
        int ll = y_lens[bb];
        int last = sh_last[bb];
        int s = 0;
        for (int t = NT - 1; t >= 0; --t) {
            if (t == ll - 1)      s = last;
            else if (t < ll - 1)  s = (int)g_bp[(size_t)t * (NB * NK) + (bb << 10) + s];
            else                  s = 0;
            g_crf[(bb << 7) + t] = s;
            out[1 + (bb << 7) + t] = (float)s;
        }
    }
}

// ---------------- final scalar reductions ----------------
__global__ __launch_bounds__(512) void final_kernel(const int* __restrict__ y,
                                                    const int* __restrict__ y_lens,
                                                    float* __restrict__ out)
{
    __shared__ float sh_emy[NB], sh_lse[NB], sh_tr[NB], sh_mp[NB];
    __shared__ float sh_sup[NB], sh_eqc[NB], sh_pc[NB], sh_ovc[NB];
    __shared__ float sh_eqs[NB], sh_ps[NB], sh_ovs[NB];
    int tid = threadIdx.x;
    int b = tid >> 5, lane = tid & 31;
    int len = y_lens[b];
    float emy = 0.f, lse = 0.f, tr = 0.f, mp = 0.f;
    float sup = 0.f, eqc = 0.f, pc = 0.f, ovc = 0.f, eqs = 0.f, ps = 0.f, ovs = 0.f;
    for (int t = lane; t < NT; t += 32) {
        int row = (b << 7) + t;
        if (t < len) {
            emy += g_emy[row];
            lse += g_rowlse[row];
            mp  += g_maxprob[row];
            int yv = y[row];
            int cp = g_crf[row];
            int sp = g_smpred[row];
            sup += (yv > 0) ? 1.f : 0.f;
            eqc += (cp == yv) ? 1.f : 0.f;
            pc  += (cp > 0) ? 1.f : 0.f;
            ovc += (cp > 0 && yv > 0) ? 1.f : 0.f;
            eqs += (sp == yv) ? 1.f : 0.f;
            ps  += (sp > 0) ? 1.f : 0.f;
            ovs += (sp > 0 && yv > 0) ? 1.f : 0.f;
        }
        if (t < NT - 1 && t < len - 1)
            tr += g_transition[(size_t)y[(b << 7) + t] * NK + y[(b << 7) + t + 1]];
    }
#pragma unroll
    for (int off = 16; off; off >>= 1) {
        emy += __shfl_xor_sync(0xffffffffu, emy, off);
        lse += __shfl_xor_sync(0xffffffffu, lse, off);
        tr  += __shfl_xor_sync(0xffffffffu, tr,  off);
        mp  += __shfl_xor_sync(0xffffffffu, mp,  off);
        sup += __shfl_xor_sync(0xffffffffu, sup, off);
        eqc += __shfl_xor_sync(0xffffffffu, eqc, off);
        pc  += __shfl_xor_sync(0xffffffffu, pc,  off);
        ovc += __shfl_xor_sync(0xffffffffu, ovc, off);
        eqs += __shfl_xor_sync(0xffffffffu, eqs, off);
        ps  += __shfl_xor_sync(0xffffffffu, ps,  off);
        ovs += __shfl_xor_sync(0xffffffffu, ovs, off);
    }
    if (lane == 0) {
        sh_emy[b] = emy; sh_lse[b] = lse; sh_tr[b] = tr; sh_mp[b] = mp;
        sh_sup[b] = sup; sh_eqc[b] = eqc; sh_pc[b] = pc; sh_ovc[b] = ovc;
        sh_eqs[b] = eqs; sh_ps[b] = ps; sh_ovs[b] = ovs;
    }
    __syncthreads();
    if (tid == 0) {
        float totlen = 0.f;
        float sZ = 0.f, sZa = 0.f, sExact = 0.f, sApprox = 0.f, sLocal = 0.f, sMp = 0.f;
        float tsup = 0.f, teqc = 0.f, tpc = 0.f, tovc = 0.f, teqs = 0.f, tps = 0.f, tovs = 0.f;
        for (int bb = 0; bb < NB; bb++) {
            totlen += (float)y_lens[bb];
            float logpot = sh_emy[bb] + sh_tr[bb];
            sZ  += g_logZ[bb];
            sZa += g_logZa[bb];
            sExact  += logpot - g_logZ[bb];
            sApprox += logpot - g_logZa[bb];
            sLocal  += sh_emy[bb] - sh_lse[bb];
            sMp     += sh_mp[bb];
            tsup += sh_sup[bb]; teqc += sh_eqc[bb]; tpc += sh_pc[bb]; tovc += sh_ovc[bb];
            teqs += sh_eqs[bb]; tps += sh_ps[bb]; tovs += sh_ovs[bb];
        }
        float exactv  = -sExact / (float)NB;
        float approxv = -sApprox / (float)NB;
        float localv  = sLocal / totlen;
        float maxpv   = sMp / totlen;
        float loss    = approxv + 0.1f * localv;

        float crf_acc = teqc / totlen;
        float crf_prec = (tpc > 0.f) ? tovc / fmaxf(tpc, 1.f) : 0.f;
        float crf_recl = tovc / fmaxf(tsup, 1.f);
        float crf_f1 = (crf_prec > 0.f)
            ? 2.f * crf_prec * crf_recl / fmaxf(crf_prec + crf_recl, 1e-12f) : 0.f;

        float sm_acc = teqs / totlen;
        float sm_prec = (tps > 0.f) ? tovs / fmaxf(tps, 1.f) : 0.f;
        float sm_recl = tovs / fmaxf(tsup, 1.f);
        float sm_f1 = (sm_prec > 0.f)
            ? 2.f * sm_prec * sm_recl / fmaxf(sm_prec + sm_recl, 1e-12f) : 0.f;

        out[0]    = loss;
        out[2049] = sZ / (float)NB;
        out[2050] = sZa / (float)NB;
        out[2051] = exactv;
        out[2052] = localv;
        out[2053] = maxpv;
        out[2054] = crf_acc;
        out[2055] = crf_f1;
        out[2056] = sm_acc;
        out[2057] = sm_f1;
    }
}

// ---------------- launch ----------------
extern "C" void kernel_launch(void* const* d_in, const int* in_sizes, int n_in,
                              void* d_out, int out_size) {
    const float* x_emb = (const float*)d_in[0];
    const float* S     = (const float*)d_in[1];
    const int*   y     = (const int*)d_in[2];
    const int*   lens  = (const int*)d_in[3];
    float* out = (float*)d_out;

    static int smem_set = 0;
    if (!smem_set) {
        cudaFuncSetAttribute(persist2, cudaFuncAttributeMaxDynamicSharedMemorySize, 131072);
        smem_set = 1;
    }

    k_gemm_tr<<<dim3(16, 16), 256>>>(S);
    k_gemm_em<<<dim3(16, 32), 256>>>(x_emb, S);
    topk_kernel<<<NBT, 512>>>(lens);
    rowstats_kernel<<<256, 256>>>(y);
    persist2<<<144, 128, 131072>>>(lens);
    trace_kernel<<<1, 512>>>(lens, out);
    final_kernel<<<1, 512>>>(y, lens, out);
}